// round 1
// baseline (speedup 1.0000x reference)
#include <cuda_runtime.h>

#define N_I 500000
#define N_H 200000
#define F_I 32
#define F_H 16
#define EF  8
#define E1  2000000
#define E2  2000000

// Scratch: per-source-node reduced edge-weight vectors y[n][8] and bias-dot z[n]
__device__ float g_y_h[N_H * EF];
__device__ float g_z_h[N_H];
__device__ float g_y_i[N_I * EF];
__device__ float g_z_i[N_I];

// --------------------------------------------------------------------------
// Precompute for house sources: y_h[n,k] = sum_f x_house[n,f] * W_edge[f,k]
//                               z_h[n]   = sum_f x_house[n,f] * b_edge[f]
// --------------------------------------------------------------------------
__global__ void __launch_bounds__(256)
pre_house_kernel(const float* __restrict__ x_house,
                 const float* __restrict__ W_edge,   // [F_H, EF]
                 const float* __restrict__ b_edge)   // [F_H]
{
    __shared__ float sW[F_H * EF];
    __shared__ float sb[F_H];
    int t = threadIdx.x;
    if (t < F_H * EF) sW[t] = W_edge[t];
    if (t < F_H)      sb[t] = b_edge[t];
    __syncthreads();

    int n = blockIdx.x * blockDim.x + t;
    if (n >= N_H) return;

    float x[F_H];
    const float4* xr = reinterpret_cast<const float4*>(x_house + (size_t)n * F_H);
#pragma unroll
    for (int i = 0; i < F_H / 4; i++) {
        float4 v = xr[i];
        x[4*i+0] = v.x; x[4*i+1] = v.y; x[4*i+2] = v.z; x[4*i+3] = v.w;
    }

    float y[EF];
#pragma unroll
    for (int k = 0; k < EF; k++) y[k] = 0.f;
    float z = 0.f;
#pragma unroll
    for (int f = 0; f < F_H; f++) {
        float xf = x[f];
#pragma unroll
        for (int k = 0; k < EF; k++) y[k] = fmaf(xf, sW[f*EF + k], y[k]);
        z = fmaf(xf, sb[f], z);
    }

    float4* yo = reinterpret_cast<float4*>(g_y_h + (size_t)n * EF);
    yo[0] = make_float4(y[0], y[1], y[2], y[3]);
    yo[1] = make_float4(y[4], y[5], y[6], y[7]);
    g_z_h[n] = z;
}

// --------------------------------------------------------------------------
// Precompute for indivi sources (F_I=32) AND initialize the output with the
// fused root transform: out[n] = x[n]·(Wr_h + Wr_i) + bias_h + bias_i
// --------------------------------------------------------------------------
__global__ void __launch_bounds__(256)
pre_indivi_kernel(const float* __restrict__ x_indivi,
                  const float* __restrict__ W_edge,   // [F_I, EF]
                  const float* __restrict__ b_edge,   // [F_I]
                  const float* __restrict__ W_root_h, // [1, F_I]
                  const float* __restrict__ W_root_i, // [1, F_I]
                  const float* __restrict__ bias_h,   // [1]
                  const float* __restrict__ bias_i,   // [1]
                  float* __restrict__ out)
{
    __shared__ float sW[F_I * EF];   // 256 floats
    __shared__ float sb[F_I];
    __shared__ float sWr[F_I];       // Wr_h + Wr_i summed
    __shared__ float sbias;
    int t = threadIdx.x;
    sW[t] = W_edge[t];               // blockDim == 256 == F_I*EF
    if (t < F_I) {
        sb[t]  = b_edge[t];
        sWr[t] = W_root_h[t] + W_root_i[t];
    }
    if (t == 0) sbias = bias_h[0] + bias_i[0];
    __syncthreads();

    int n = blockIdx.x * blockDim.x + t;
    if (n >= N_I) return;

    float x[F_I];
    const float4* xr = reinterpret_cast<const float4*>(x_indivi + (size_t)n * F_I);
#pragma unroll
    for (int i = 0; i < F_I / 4; i++) {
        float4 v = xr[i];
        x[4*i+0] = v.x; x[4*i+1] = v.y; x[4*i+2] = v.z; x[4*i+3] = v.w;
    }

    float y[EF];
#pragma unroll
    for (int k = 0; k < EF; k++) y[k] = 0.f;
    float z = 0.f;
    float root = sbias;
#pragma unroll
    for (int f = 0; f < F_I; f++) {
        float xf = x[f];
#pragma unroll
        for (int k = 0; k < EF; k++) y[k] = fmaf(xf, sW[f*EF + k], y[k]);
        z    = fmaf(xf, sb[f],  z);
        root = fmaf(xf, sWr[f], root);
    }

    float4* yo = reinterpret_cast<float4*>(g_y_i + (size_t)n * EF);
    yo[0] = make_float4(y[0], y[1], y[2], y[3]);
    yo[1] = make_float4(y[4], y[5], y[6], y[7]);
    g_z_i[n] = z;
    out[n]   = root;   // initializes the output (it is poisoned before timing)
}

// --------------------------------------------------------------------------
// Edge scatter: msg_e = ea[e]·y[src_e] + z[src_e];  out[dst_e] += msg_e
// --------------------------------------------------------------------------
__global__ void __launch_bounds__(256)
edge_kernel(const float* __restrict__ ea,    // [E, 8]
            const int*   __restrict__ src,
            const int*   __restrict__ dst,
            const float* __restrict__ y,     // [N_src, 8]
            const float* __restrict__ z,     // [N_src]
            float* __restrict__ out,
            int E)
{
    int e = blockIdx.x * blockDim.x + threadIdx.x;
    if (e >= E) return;

    int s = __ldg(src + e);
    int d = __ldg(dst + e);

    const float4* ar = reinterpret_cast<const float4*>(ea + (size_t)e * EF);
    float4 a0 = __ldg(ar);
    float4 a1 = __ldg(ar + 1);

    const float4* yr = reinterpret_cast<const float4*>(y + (size_t)s * EF);
    float4 y0 = __ldg(yr);
    float4 y1 = __ldg(yr + 1);

    float m = __ldg(z + s);
    m = fmaf(a0.x, y0.x, m);
    m = fmaf(a0.y, y0.y, m);
    m = fmaf(a0.z, y0.z, m);
    m = fmaf(a0.w, y0.w, m);
    m = fmaf(a1.x, y1.x, m);
    m = fmaf(a1.y, y1.y, m);
    m = fmaf(a1.z, y1.z, m);
    m = fmaf(a1.w, y1.w, m);

    atomicAdd(out + d, m);
}

// --------------------------------------------------------------------------
extern "C" void kernel_launch(void* const* d_in, const int* in_sizes, int n_in,
                              void* d_out, int out_size)
{
    const float* x_indivi      = (const float*)d_in[0];
    const float* x_house       = (const float*)d_in[1];
    const float* edge_attr_h2i = (const float*)d_in[2];
    const float* edge_attr_i2i = (const float*)d_in[3];
    const float* W_edge_h2i    = (const float*)d_in[4];
    const float* b_edge_h2i    = (const float*)d_in[5];
    const float* W_edge_i2i    = (const float*)d_in[6];
    const float* b_edge_i2i    = (const float*)d_in[7];
    const float* W_root_h2i    = (const float*)d_in[8];
    const float* bias_h2i      = (const float*)d_in[9];
    const float* W_root_i2i    = (const float*)d_in[10];
    const float* bias_i2i      = (const float*)d_in[11];
    const int*   src_h2i       = (const int*)d_in[12];
    const int*   dst_h2i       = (const int*)d_in[13];
    const int*   src_i2i       = (const int*)d_in[14];
    const int*   dst_i2i       = (const int*)d_in[15];
    float* out = (float*)d_out;

    float* y_h; float* z_h; float* y_i; float* z_i;
    cudaGetSymbolAddress((void**)&y_h, g_y_h);
    cudaGetSymbolAddress((void**)&z_h, g_z_h);
    cudaGetSymbolAddress((void**)&y_i, g_y_i);
    cudaGetSymbolAddress((void**)&z_i, g_z_i);

    // Node precompute (indivi kernel also initializes out with root+bias terms)
    pre_indivi_kernel<<<(N_I + 255) / 256, 256>>>(
        x_indivi, W_edge_i2i, b_edge_i2i, W_root_h2i, W_root_i2i,
        bias_h2i, bias_i2i, out);
    pre_house_kernel<<<(N_H + 255) / 256, 256>>>(
        x_house, W_edge_h2i, b_edge_h2i);

    // Edge scatter (stream-ordered after precompute)
    edge_kernel<<<(E1 + 255) / 256, 256>>>(
        edge_attr_h2i, src_h2i, dst_h2i, y_h, z_h, out, E1);
    edge_kernel<<<(E2 + 255) / 256, 256>>>(
        edge_attr_i2i, src_i2i, dst_i2i, y_i, z_i, out, E2);
}

// round 2
// speedup vs baseline: 1.2554x; 1.2554x over previous
#include <cuda_runtime.h>
#include <cuda_fp16.h>

#define N_I 500000
#define N_H 200000
#define F_I 32
#define F_H 16
#define EF  8
#define E1  2000000
#define E2  2000000

#define BLOCKS_I ((N_I + 255) / 256)   // 1954
#define BLOCKS_H ((N_H + 255) / 256)   // 782

// Packed per-source-node record, 32 bytes (one L2 sector) per node:
//   floats [0..3] : y[0..7] as 8 x fp16 (packed pairs)
//   float  [4]    : z (fp32)
//   floats [5..7] : pad
__device__ __align__(32) float g_rec_h[(size_t)N_H * 8];
__device__ __align__(32) float g_rec_i[(size_t)N_I * 8];

__device__ __forceinline__ float pack2h(float a, float b) {
    __half2 h = __floats2half2_rn(a, b);
    return __uint_as_float(*reinterpret_cast<unsigned*>(&h));
}

// --------------------------------------------------------------------------
// Fused node precompute: blocks [0, BLOCKS_I) handle indivi (and init out),
// blocks [BLOCKS_I, BLOCKS_I+BLOCKS_H) handle house.
// --------------------------------------------------------------------------
__global__ void __launch_bounds__(256)
pre_kernel(const float* __restrict__ x_indivi,
           const float* __restrict__ x_house,
           const float* __restrict__ W_edge_i,  // [F_I, EF]
           const float* __restrict__ b_edge_i,  // [F_I]
           const float* __restrict__ W_edge_h,  // [F_H, EF]
           const float* __restrict__ b_edge_h,  // [F_H]
           const float* __restrict__ W_root_h,  // [1, F_I]
           const float* __restrict__ W_root_i,  // [1, F_I]
           const float* __restrict__ bias_h,    // [1]
           const float* __restrict__ bias_i,    // [1]
           float* __restrict__ out)
{
    __shared__ float sW[F_I * EF];   // 256 floats (max of both paths)
    __shared__ float sb[F_I];
    __shared__ float sWr[F_I];
    __shared__ float sbias;
    int t = threadIdx.x;

    if (blockIdx.x < BLOCKS_I) {
        // ----- indivi path -----
        sW[t] = W_edge_i[t];                       // 256 == F_I*EF
        if (t < F_I) {
            sb[t]  = b_edge_i[t];
            sWr[t] = W_root_h[t] + W_root_i[t];
        }
        if (t == 0) sbias = bias_h[0] + bias_i[0];
        __syncthreads();

        int n = blockIdx.x * 256 + t;
        if (n >= N_I) return;

        float x[F_I];
        const float4* xr = reinterpret_cast<const float4*>(x_indivi + (size_t)n * F_I);
#pragma unroll
        for (int i = 0; i < F_I / 4; i++) {
            float4 v = xr[i];
            x[4*i+0] = v.x; x[4*i+1] = v.y; x[4*i+2] = v.z; x[4*i+3] = v.w;
        }

        float y[EF];
#pragma unroll
        for (int k = 0; k < EF; k++) y[k] = 0.f;
        float z = 0.f;
        float root = sbias;
#pragma unroll
        for (int f = 0; f < F_I; f++) {
            float xf = x[f];
#pragma unroll
            for (int k = 0; k < EF; k++) y[k] = fmaf(xf, sW[f*EF + k], y[k]);
            z    = fmaf(xf, sb[f],  z);
            root = fmaf(xf, sWr[f], root);
        }

        float4* ro = reinterpret_cast<float4*>(g_rec_i + (size_t)n * 8);
        ro[0] = make_float4(pack2h(y[0], y[1]), pack2h(y[2], y[3]),
                            pack2h(y[4], y[5]), pack2h(y[6], y[7]));
        ro[1] = make_float4(z, 0.f, 0.f, 0.f);
        out[n] = root;
    } else {
        // ----- house path -----
        if (t < F_H * EF) sW[t] = W_edge_h[t];
        if (t < F_H)      sb[t] = b_edge_h[t];
        __syncthreads();

        int n = (blockIdx.x - BLOCKS_I) * 256 + t;
        if (n >= N_H) return;

        float x[F_H];
        const float4* xr = reinterpret_cast<const float4*>(x_house + (size_t)n * F_H);
#pragma unroll
        for (int i = 0; i < F_H / 4; i++) {
            float4 v = xr[i];
            x[4*i+0] = v.x; x[4*i+1] = v.y; x[4*i+2] = v.z; x[4*i+3] = v.w;
        }

        float y[EF];
#pragma unroll
        for (int k = 0; k < EF; k++) y[k] = 0.f;
        float z = 0.f;
#pragma unroll
        for (int f = 0; f < F_H; f++) {
            float xf = x[f];
#pragma unroll
            for (int k = 0; k < EF; k++) y[k] = fmaf(xf, sW[f*EF + k], y[k]);
            z = fmaf(xf, sb[f], z);
        }

        float4* ro = reinterpret_cast<float4*>(g_rec_h + (size_t)n * 8);
        ro[0] = make_float4(pack2h(y[0], y[1]), pack2h(y[2], y[3]),
                            pack2h(y[4], y[5]), pack2h(y[6], y[7]));
        ro[1] = make_float4(z, 0.f, 0.f, 0.f);
    }
}

// --------------------------------------------------------------------------
// Fused edge scatter for both relations.
//   msg_e = ea[e] . y[src_e] + z[src_e];  out[dst_e] += msg_e
// One 32B-sector gather per edge (fp16 y + fp32 z in one record).
// --------------------------------------------------------------------------
__device__ __forceinline__ void
edge_body(const float* __restrict__ ea, const int* __restrict__ src,
          const int* __restrict__ dst, const float* __restrict__ rec,
          float* __restrict__ out, int e)
{
    int s = __ldg(src + e);
    int d = __ldg(dst + e);

    const float4* ar = reinterpret_cast<const float4*>(ea + (size_t)e * EF);
    float4 a0 = __ldg(ar);
    float4 a1 = __ldg(ar + 1);

    float4 v = __ldg(reinterpret_cast<const float4*>(rec + (size_t)s * 8));
    float  z = __ldg(rec + (size_t)s * 8 + 4);   // same 32B sector -> L1 hit

    __half2 h01 = *reinterpret_cast<__half2*>(&v.x);
    __half2 h23 = *reinterpret_cast<__half2*>(&v.y);
    __half2 h45 = *reinterpret_cast<__half2*>(&v.z);
    __half2 h67 = *reinterpret_cast<__half2*>(&v.w);
    float2 f01 = __half22float2(h01);
    float2 f23 = __half22float2(h23);
    float2 f45 = __half22float2(h45);
    float2 f67 = __half22float2(h67);

    float m = z;
    m = fmaf(a0.x, f01.x, m);
    m = fmaf(a0.y, f01.y, m);
    m = fmaf(a0.z, f23.x, m);
    m = fmaf(a0.w, f23.y, m);
    m = fmaf(a1.x, f45.x, m);
    m = fmaf(a1.y, f45.y, m);
    m = fmaf(a1.z, f67.x, m);
    m = fmaf(a1.w, f67.y, m);

    atomicAdd(out + d, m);
}

__global__ void __launch_bounds__(256)
edge_fused_kernel(const float* __restrict__ ea1,
                  const int*   __restrict__ src1,
                  const int*   __restrict__ dst1,
                  const float* __restrict__ ea2,
                  const int*   __restrict__ src2,
                  const int*   __restrict__ dst2,
                  float* __restrict__ out)
{
    int e = blockIdx.x * 256 + threadIdx.x;
    if (e < E1) {
        edge_body(ea1, src1, dst1, g_rec_h, out, e);
    } else {
        int e2 = e - E1;
        if (e2 < E2)
            edge_body(ea2, src2, dst2, g_rec_i, out, e2);
    }
}

// --------------------------------------------------------------------------
extern "C" void kernel_launch(void* const* d_in, const int* in_sizes, int n_in,
                              void* d_out, int out_size)
{
    const float* x_indivi      = (const float*)d_in[0];
    const float* x_house       = (const float*)d_in[1];
    const float* edge_attr_h2i = (const float*)d_in[2];
    const float* edge_attr_i2i = (const float*)d_in[3];
    const float* W_edge_h2i    = (const float*)d_in[4];
    const float* b_edge_h2i    = (const float*)d_in[5];
    const float* W_edge_i2i    = (const float*)d_in[6];
    const float* b_edge_i2i    = (const float*)d_in[7];
    const float* W_root_h2i    = (const float*)d_in[8];
    const float* bias_h2i      = (const float*)d_in[9];
    const float* W_root_i2i    = (const float*)d_in[10];
    const float* bias_i2i      = (const float*)d_in[11];
    const int*   src_h2i       = (const int*)d_in[12];
    const int*   dst_h2i       = (const int*)d_in[13];
    const int*   src_i2i       = (const int*)d_in[14];
    const int*   dst_i2i       = (const int*)d_in[15];
    float* out = (float*)d_out;

    pre_kernel<<<BLOCKS_I + BLOCKS_H, 256>>>(
        x_indivi, x_house, W_edge_i2i, b_edge_i2i, W_edge_h2i, b_edge_h2i,
        W_root_h2i, W_root_i2i, bias_h2i, bias_i2i, out);

    int total_edges = E1 + E2;
    edge_fused_kernel<<<(total_edges + 255) / 256, 256>>>(
        edge_attr_h2i, src_h2i, dst_h2i,
        edge_attr_i2i, src_i2i, dst_i2i, out);
}

// round 3
// speedup vs baseline: 1.3736x; 1.0942x over previous
#include <cuda_runtime.h>
#include <cuda_fp16.h>

#define N_I 500000
#define N_H 200000
#define F_I 32
#define F_H 16
#define EF  8
#define E1  2000000
#define E2  2000000

#define BLOCKS_I ((N_I + 255) / 256)   // 1954
#define BLOCKS_H ((N_H + 255) / 256)   // 782

// Packed per-source-node record, 32 bytes (one L2 sector) per node:
//   floats [0..3] : y[0..7] as 8 x fp16 (packed pairs)
//   float  [4]    : z (fp32)
//   floats [5..7] : pad
__device__ __align__(32) float g_rec_h[(size_t)N_H * 8];
__device__ __align__(32) float g_rec_i[(size_t)N_I * 8];

__device__ __forceinline__ float pack2h(float a, float b) {
    __half2 h = __floats2half2_rn(a, b);
    return __uint_as_float(*reinterpret_cast<unsigned*>(&h));
}

// --------------------------------------------------------------------------
// Fused node precompute with coalesced smem staging.
// blocks [0, BLOCKS_I): indivi (also init out); [BLOCKS_I, +BLOCKS_H): house.
// --------------------------------------------------------------------------
#define STRIDE_I 33   // padded row stride (floats) for indivi staging
#define STRIDE_H 17   // padded row stride (floats) for house staging

__global__ void __launch_bounds__(256)
pre_kernel(const float* __restrict__ x_indivi,
           const float* __restrict__ x_house,
           const float* __restrict__ W_edge_i,  // [F_I, EF]
           const float* __restrict__ b_edge_i,  // [F_I]
           const float* __restrict__ W_edge_h,  // [F_H, EF]
           const float* __restrict__ b_edge_h,  // [F_H]
           const float* __restrict__ W_root_h,  // [1, F_I]
           const float* __restrict__ W_root_i,  // [1, F_I]
           const float* __restrict__ bias_h,    // [1]
           const float* __restrict__ bias_i,    // [1]
           float* __restrict__ out)
{
    __shared__ float sx[256 * STRIDE_I];   // 33.8 KB (house path uses a prefix)
    __shared__ float sW[F_I * EF];
    __shared__ float sb[F_I];
    __shared__ float sWr[F_I];
    __shared__ float sbias;
    int t = threadIdx.x;

    if (blockIdx.x < BLOCKS_I) {
        // ----- indivi path -----
        sW[t] = W_edge_i[t];                       // 256 == F_I*EF
        if (t < F_I) {
            sb[t]  = b_edge_i[t];
            sWr[t] = W_root_h[t] + W_root_i[t];
        }
        if (t == 0) sbias = bias_h[0] + bias_i[0];

        // Coalesced staging: 256 rows x 32 floats = 2048 float4
        int base = blockIdx.x * 256;
        const float4* x4 = reinterpret_cast<const float4*>(x_indivi);
        long gbase = (long)base * (F_I / 4);
        long gmax  = (long)N_I * (F_I / 4);
#pragma unroll
        for (int i = 0; i < 8; i++) {
            long gidx = gbase + t + i * 256;
            if (gidx < gmax) {
                float4 v = x4[gidx];
                int loc = t + i * 256;          // float4 index within block chunk
                int row = loc >> 3;             // 8 float4 per row
                int col = loc & 7;
                float* p = sx + row * STRIDE_I + col * 4;
                p[0] = v.x; p[1] = v.y; p[2] = v.z; p[3] = v.w;
            }
        }
        __syncthreads();

        int n = base + t;
        if (n >= N_I) return;

        const float* xr = sx + t * STRIDE_I;
        float y[EF];
#pragma unroll
        for (int k = 0; k < EF; k++) y[k] = 0.f;
        float z = 0.f;
        float root = sbias;
#pragma unroll
        for (int f = 0; f < F_I; f++) {
            float xf = xr[f];
#pragma unroll
            for (int k = 0; k < EF; k++) y[k] = fmaf(xf, sW[f*EF + k], y[k]);
            z    = fmaf(xf, sb[f],  z);
            root = fmaf(xf, sWr[f], root);
        }

        float4* ro = reinterpret_cast<float4*>(g_rec_i + (size_t)n * 8);
        ro[0] = make_float4(pack2h(y[0], y[1]), pack2h(y[2], y[3]),
                            pack2h(y[4], y[5]), pack2h(y[6], y[7]));
        ro[1] = make_float4(z, 0.f, 0.f, 0.f);
        out[n] = root;
    } else {
        // ----- house path -----
        if (t < F_H * EF) sW[t] = W_edge_h[t];
        if (t < F_H)      sb[t] = b_edge_h[t];

        int base = (blockIdx.x - BLOCKS_I) * 256;
        const float4* x4 = reinterpret_cast<const float4*>(x_house);
        long gbase = (long)base * (F_H / 4);
        long gmax  = (long)N_H * (F_H / 4);
#pragma unroll
        for (int i = 0; i < 4; i++) {
            long gidx = gbase + t + i * 256;
            if (gidx < gmax) {
                float4 v = x4[gidx];
                int loc = t + i * 256;
                int row = loc >> 2;             // 4 float4 per row
                int col = loc & 3;
                float* p = sx + row * STRIDE_H + col * 4;
                p[0] = v.x; p[1] = v.y; p[2] = v.z; p[3] = v.w;
            }
        }
        __syncthreads();

        int n = base + t;
        if (n >= N_H) return;

        const float* xr = sx + t * STRIDE_H;
        float y[EF];
#pragma unroll
        for (int k = 0; k < EF; k++) y[k] = 0.f;
        float z = 0.f;
#pragma unroll
        for (int f = 0; f < F_H; f++) {
            float xf = xr[f];
#pragma unroll
            for (int k = 0; k < EF; k++) y[k] = fmaf(xf, sW[f*EF + k], y[k]);
            z = fmaf(xf, sb[f], z);
        }

        float4* ro = reinterpret_cast<float4*>(g_rec_h + (size_t)n * 8);
        ro[0] = make_float4(pack2h(y[0], y[1]), pack2h(y[2], y[3]),
                            pack2h(y[4], y[5]), pack2h(y[6], y[7]));
        ro[1] = make_float4(z, 0.f, 0.f, 0.f);
    }
}

// --------------------------------------------------------------------------
// Fused edge scatter for both relations.
//   msg_e = ea[e] . y[src_e] + z[src_e];  out[dst_e] += msg_e
// One 32B-sector gather per edge (fp16 y + fp32 z in one record).
// --------------------------------------------------------------------------
__device__ __forceinline__ void
edge_body(const float* __restrict__ ea, const int* __restrict__ src,
          const int* __restrict__ dst, const float* __restrict__ rec,
          float* __restrict__ out, int e)
{
    int s = __ldg(src + e);
    int d = __ldg(dst + e);

    const float4* ar = reinterpret_cast<const float4*>(ea + (size_t)e * EF);
    float4 a0 = __ldg(ar);
    float4 a1 = __ldg(ar + 1);

    float4 v = __ldg(reinterpret_cast<const float4*>(rec + (size_t)s * 8));
    float  z = __ldg(rec + (size_t)s * 8 + 4);   // same 32B sector -> L1 hit

    __half2 h01 = *reinterpret_cast<__half2*>(&v.x);
    __half2 h23 = *reinterpret_cast<__half2*>(&v.y);
    __half2 h45 = *reinterpret_cast<__half2*>(&v.z);
    __half2 h67 = *reinterpret_cast<__half2*>(&v.w);
    float2 f01 = __half22float2(h01);
    float2 f23 = __half22float2(h23);
    float2 f45 = __half22float2(h45);
    float2 f67 = __half22float2(h67);

    float m = z;
    m = fmaf(a0.x, f01.x, m);
    m = fmaf(a0.y, f01.y, m);
    m = fmaf(a0.z, f23.x, m);
    m = fmaf(a0.w, f23.y, m);
    m = fmaf(a1.x, f45.x, m);
    m = fmaf(a1.y, f45.y, m);
    m = fmaf(a1.z, f67.x, m);
    m = fmaf(a1.w, f67.y, m);

    atomicAdd(out + d, m);
}

__global__ void __launch_bounds__(256)
edge_fused_kernel(const float* __restrict__ ea1,
                  const int*   __restrict__ src1,
                  const int*   __restrict__ dst1,
                  const float* __restrict__ ea2,
                  const int*   __restrict__ src2,
                  const int*   __restrict__ dst2,
                  float* __restrict__ out)
{
    int e = blockIdx.x * 256 + threadIdx.x;
    if (e < E1) {
        edge_body(ea1, src1, dst1, g_rec_h, out, e);
    } else {
        int e2 = e - E1;
        if (e2 < E2)
            edge_body(ea2, src2, dst2, g_rec_i, out, e2);
    }
}

// --------------------------------------------------------------------------
extern "C" void kernel_launch(void* const* d_in, const int* in_sizes, int n_in,
                              void* d_out, int out_size)
{
    const float* x_indivi      = (const float*)d_in[0];
    const float* x_house       = (const float*)d_in[1];
    const float* edge_attr_h2i = (const float*)d_in[2];
    const float* edge_attr_i2i = (const float*)d_in[3];
    const float* W_edge_h2i    = (const float*)d_in[4];
    const float* b_edge_h2i    = (const float*)d_in[5];
    const float* W_edge_i2i    = (const float*)d_in[6];
    const float* b_edge_i2i    = (const float*)d_in[7];
    const float* W_root_h2i    = (const float*)d_in[8];
    const float* bias_h2i      = (const float*)d_in[9];
    const float* W_root_i2i    = (const float*)d_in[10];
    const float* bias_i2i      = (const float*)d_in[11];
    const int*   src_h2i       = (const int*)d_in[12];
    const int*   dst_h2i       = (const int*)d_in[13];
    const int*   src_i2i       = (const int*)d_in[14];
    const int*   dst_i2i       = (const int*)d_in[15];
    float* out = (float*)d_out;

    pre_kernel<<<BLOCKS_I + BLOCKS_H, 256>>>(
        x_indivi, x_house, W_edge_i2i, b_edge_i2i, W_edge_h2i, b_edge_h2i,
        W_root_h2i, W_root_i2i, bias_h2i, bias_i2i, out);

    int total_edges = E1 + E2;
    edge_fused_kernel<<<(total_edges + 255) / 256, 256>>>(
        edge_attr_h2i, src_h2i, dst_h2i,
        edge_attr_i2i, src_i2i, dst_i2i, out);
}